// round 16
// baseline (speedup 1.0000x reference)
#include <cuda_runtime.h>
#include <cuda_bf16.h>

#define N_NODES 100000
#define N_EDGES 1600000
#define H 64
#define SCAN_NB ((N_NODES + 255) / 256)   // 391

// ---------------- scratch (device globals; no allocation allowed) ----------------
__device__ float g_q[N_NODES * H];
__device__ __nv_bfloat16 g_kbf[N_NODES * H];  // k in bf16 (gathered 16x per node)
__device__ __nv_bfloat16 g_vbf[N_NODES * H];  // v in bf16 (gathered 16x per node)
__device__ float g_h[N_NODES * H];   // current node features
__device__ float g_o[N_NODES * H];   // skip accumulator / conv1 output
__device__ int   g_cnt[N_NODES];     // zero at process start (BSS); re-zeroed by scan_fill each launch
__device__ int   g_off[N_NODES + 1];
__device__ int   g_cur[N_NODES];
__device__ int   g_srcs[N_EDGES];    // CSR-permuted sources (fp32 path — precision budget closed)
__device__ float2 g_ea[N_EDGES];     // CSR-permuted edge_attr (fp32)
__device__ float g_bnsum[H];
__device__ float g_bnsq[H];
__device__ int   g_bsum[512];
__device__ int   g_bpre[512];

__device__ __forceinline__ float leakyf(float x) { return x >= 0.f ? x : 0.01f * x; }

// ---- packed f32x2 ops (Blackwell FFMA2/FADD2/FMUL2; PTX-only) ----
__device__ __forceinline__ float2 ffma2(float2 a, float2 b, float2 c) {
    float2 d;
    asm("fma.rn.f32x2 %0, %1, %2, %3;"
        : "=l"(*reinterpret_cast<unsigned long long*>(&d))
        : "l"(*reinterpret_cast<unsigned long long*>(&a)),
          "l"(*reinterpret_cast<unsigned long long*>(&b)),
          "l"(*reinterpret_cast<unsigned long long*>(&c)));
    return d;
}
__device__ __forceinline__ float2 fadd2(float2 a, float2 b) {
    float2 d;
    asm("add.rn.f32x2 %0, %1, %2;"
        : "=l"(*reinterpret_cast<unsigned long long*>(&d))
        : "l"(*reinterpret_cast<unsigned long long*>(&a)),
          "l"(*reinterpret_cast<unsigned long long*>(&b)));
    return d;
}
__device__ __forceinline__ float2 fmul2(float2 a, float2 b) {
    float2 d;
    asm("mul.rn.f32x2 %0, %1, %2;"
        : "=l"(*reinterpret_cast<unsigned long long*>(&d))
        : "l"(*reinterpret_cast<unsigned long long*>(&a)),
          "l"(*reinterpret_cast<unsigned long long*>(&b)));
    return d;
}

// ---------------- CSR build ----------------
__global__ void hist_kernel(const int* __restrict__ edge_index) {
    int i = blockIdx.x * blockDim.x + threadIdx.x;
    if (i >= N_EDGES) return;
    int t = edge_index[N_EDGES + i];
    atomicAdd(&g_cnt[t], 1);
}

// 3-phase parallel exclusive scan of g_cnt -> g_off / g_cur
__global__ void scan_block_sums() {
    __shared__ int sh[256];
    int i = blockIdx.x * 256 + threadIdx.x;
    int v = (i < N_NODES) ? g_cnt[i] : 0;
    sh[threadIdx.x] = v;
    __syncthreads();
    for (int o = 128; o > 0; o >>= 1) {
        if (threadIdx.x < o) sh[threadIdx.x] += sh[threadIdx.x + o];
        __syncthreads();
    }
    if (threadIdx.x == 0) g_bsum[blockIdx.x] = sh[0];
}

__global__ void scan_partials() {   // 1 block, 512 threads
    __shared__ int sh[512];
    int t = threadIdx.x;
    int v = (t < SCAN_NB) ? g_bsum[t] : 0;
    sh[t] = v;
    __syncthreads();
    for (int o = 1; o < 512; o <<= 1) {
        int u = (t >= o) ? sh[t - o] : 0;
        __syncthreads();
        sh[t] += u;
        __syncthreads();
    }
    g_bpre[t] = sh[t] - v;  // exclusive prefix of block t
    if (t == SCAN_NB - 1) g_off[N_NODES] = sh[t];
}

// also re-zeroes g_cnt (for next launch) and the BN accumulators (used later
// in THIS launch by bn_stats). Deterministic: g_cnt starts zero (BSS) and is
// returned to zero by every launch before it ends.
__global__ void scan_fill() {
    __shared__ int sh[256];
    int t = threadIdx.x;
    int i = blockIdx.x * 256 + t;
    int v = (i < N_NODES) ? g_cnt[i] : 0;
    sh[t] = v;
    __syncthreads();
    for (int o = 1; o < 256; o <<= 1) {
        int u = (t >= o) ? sh[t - o] : 0;
        __syncthreads();
        sh[t] += u;
        __syncthreads();
    }
    int excl = sh[t] - v + g_bpre[blockIdx.x];
    if (i < N_NODES) { g_off[i] = excl; g_cur[i] = excl; g_cnt[i] = 0; }
    if (blockIdx.x == 0 && t < H) { g_bnsum[t] = 0.f; g_bnsq[t] = 0.f; }
}

__global__ void scatter_kernel(const int* __restrict__ edge_index,
                               const float* __restrict__ edge_attr) {
    int i = blockIdx.x * blockDim.x + threadIdx.x;
    if (i >= N_EDGES) return;
    int t = edge_index[N_EDGES + i];
    int p = atomicAdd(&g_cur[t], 1);
    g_srcs[p] = edge_index[i];
    g_ea[p] = reinterpret_cast<const float2*>(edge_attr)[i];
}

// ---------------- node transforms ----------------
// conv1: in-dim 2. one thread per (node, 4 channels). float4; k,v stored bf16.
__global__ void transform1_kernel(const float* __restrict__ x,
                                  const float* __restrict__ Wq, const float* __restrict__ bq,
                                  const float* __restrict__ Wk, const float* __restrict__ bk,
                                  const float* __restrict__ Wv, const float* __restrict__ bv,
                                  const float* __restrict__ Ws, const float* __restrict__ bs) {
    int idx = blockIdx.x * blockDim.x + threadIdx.x;
    if (idx >= N_NODES * 16) return;
    int c4 = idx & 15;            // which float4 of the 16 per row
    int n = idx >> 4;
    float2 xv = reinterpret_cast<const float2*>(x)[n];
    const float4* Wq4 = (const float4*)Wq; const float4* bq4 = (const float4*)bq;
    const float4* Wk4 = (const float4*)Wk; const float4* bk4 = (const float4*)bk;
    const float4* Wv4 = (const float4*)Wv; const float4* bv4 = (const float4*)bv;
    const float4* Ws4 = (const float4*)Ws; const float4* bs4 = (const float4*)bs;
    float4 w0, w1, b, r;
#define T1C(W4, B4) \
    w0 = W4[c4]; w1 = W4[16 + c4]; b = B4[c4]; \
    r.x = xv.x * w0.x + xv.y * w1.x + b.x; \
    r.y = xv.x * w0.y + xv.y * w1.y + b.y; \
    r.z = xv.x * w0.z + xv.y * w1.z + b.z; \
    r.w = xv.x * w0.w + xv.y * w1.w + b.w;
#define PACK_BF16_STORE(DST) \
    { \
        __nv_bfloat162 lo = __float22bfloat162_rn(make_float2(r.x, r.y)); \
        __nv_bfloat162 hi = __float22bfloat162_rn(make_float2(r.z, r.w)); \
        uint2 pk; \
        pk.x = *reinterpret_cast<unsigned int*>(&lo); \
        pk.y = *reinterpret_cast<unsigned int*>(&hi); \
        reinterpret_cast<uint2*>(DST)[idx] = pk; \
    }
    T1C(Wq4, bq4) reinterpret_cast<float4*>(g_q)[idx] = r;
    T1C(Wk4, bk4) PACK_BF16_STORE(g_kbf)
    T1C(Wv4, bv4) PACK_BF16_STORE(g_vbf)
    T1C(Ws4, bs4) reinterpret_cast<float4*>(g_o)[idx] = r;
#undef PACK_BF16_STORE
#undef T1C
}

// conv2: in-dim 64. 4 nodes per warp (R5 tiling, locked); h staged in smem;
// NEW: all 4 weight matrices staged in smem (16 KB) once per block, inner loop
// reads weights via LDS (structural floor 2 cyc/SMSP vs LDG's 4).
__global__ void transform2_kernel(const float* __restrict__ h,
                                  const float* __restrict__ Wq, const float* __restrict__ bq,
                                  const float* __restrict__ Wk, const float* __restrict__ bk,
                                  const float* __restrict__ Wv, const float* __restrict__ bv,
                                  const float* __restrict__ Ws, const float* __restrict__ bs) {
    __shared__ float hs[32 * H];        // 8 KB: 32 nodes
    __shared__ float ws[4 * H * H / 1]; // 16 KB: Wq|Wk|Wv|Ws, each HxH
    int tid = threadIdx.x;
    int nodeBase = blockIdx.x * 32;
    // stage h tile (float4 coalesced)
    for (int i = tid; i < 32 * 16; i += 256) {
        int n = nodeBase + (i >> 4);
        float4 val = (n < N_NODES) ? reinterpret_cast<const float4*>(h)[n * 16 + (i & 15)]
                                   : make_float4(0.f, 0.f, 0.f, 0.f);
        reinterpret_cast<float4*>(hs)[i] = val;
    }
    // stage weights (each matrix 4096 floats = 1024 float4)
    {
        float4* ws4 = reinterpret_cast<float4*>(ws);
        const float4* Wq4 = (const float4*)Wq;
        const float4* Wk4 = (const float4*)Wk;
        const float4* Wv4 = (const float4*)Wv;
        const float4* Ws4 = (const float4*)Ws;
        for (int i = tid; i < 1024; i += 256) {
            ws4[i]        = Wq4[i];
            ws4[1024 + i] = Wk4[i];
            ws4[2048 + i] = Wv4[i];
            ws4[3072 + i] = Ws4[i];
        }
    }
    __syncthreads();

    int wid = tid >> 5, lane = tid & 31;
    int nloc = wid * 4;           // local node base within block
    float2 aq[4], ak[4], av[4], ao[4];
    float2 bqv = reinterpret_cast<const float2*>(bq)[lane];
    float2 bkv = reinterpret_cast<const float2*>(bk)[lane];
    float2 bvv = reinterpret_cast<const float2*>(bv)[lane];
    float2 bsv = reinterpret_cast<const float2*>(bs)[lane];
#pragma unroll
    for (int nn = 0; nn < 4; nn++) { aq[nn] = bqv; ak[nn] = bkv; av[nn] = bvv; ao[nn] = bsv; }

    const float2* hs2 = reinterpret_cast<const float2*>(hs);
    const float2* wq2 = reinterpret_cast<const float2*>(ws);
    const float2* wk2 = reinterpret_cast<const float2*>(ws + H * H);
    const float2* wv2 = reinterpret_cast<const float2*>(ws + 2 * H * H);
    const float2* ws2 = reinterpret_cast<const float2*>(ws + 3 * H * H);
#pragma unroll 4
    for (int kk = 0; kk < 32; kk++) {
        float2 w0q = wq2[(2 * kk) * 32 + lane];
        float2 w1q = wq2[(2 * kk + 1) * 32 + lane];
        float2 w0k = wk2[(2 * kk) * 32 + lane];
        float2 w1k = wk2[(2 * kk + 1) * 32 + lane];
        float2 w0v = wv2[(2 * kk) * 32 + lane];
        float2 w1v = wv2[(2 * kk + 1) * 32 + lane];
        float2 w0s = ws2[(2 * kk) * 32 + lane];
        float2 w1s = ws2[(2 * kk + 1) * 32 + lane];
#pragma unroll
        for (int nn = 0; nn < 4; nn++) {
            float2 hxy = hs2[(nloc + nn) * 32 + kk];  // smem broadcast
            float2 hx2 = make_float2(hxy.x, hxy.x);
            float2 hy2 = make_float2(hxy.y, hxy.y);
            aq[nn] = ffma2(hy2, w1q, ffma2(hx2, w0q, aq[nn]));
            ak[nn] = ffma2(hy2, w1k, ffma2(hx2, w0k, ak[nn]));
            av[nn] = ffma2(hy2, w1v, ffma2(hx2, w0v, av[nn]));
            ao[nn] = ffma2(hy2, w1s, ffma2(hx2, w0s, ao[nn]));
        }
    }
#pragma unroll
    for (int nn = 0; nn < 4; nn++) {
        int n = nodeBase + nloc + nn;
        if (n < N_NODES) {
            reinterpret_cast<float2*>(g_q)[n * 32 + lane] = aq[nn];
            __nv_bfloat162 kb = __float22bfloat162_rn(ak[nn]);
            reinterpret_cast<__nv_bfloat162*>(g_kbf)[n * 32 + lane] = kb;
            __nv_bfloat162 vb = __float22bfloat162_rn(av[nn]);
            reinterpret_cast<__nv_bfloat162*>(g_vbf)[n * 32 + lane] = vb;
            reinterpret_cast<float2*>(g_o)[n * 32 + lane] = ao[nn];
        }
    }
}

// ---------------- fused attention aggregation (R11/R14 champion — LOCKED) ----
// warp per target node; 4 sub-groups of 8 lanes, one edge per group per iter;
// plain exp (shift-invariant softmax, bounded scores); packed f32x2; sum-merge.
// Intra-group shfls use the GROUP mask (groups have different trip counts).
// All loop-shape / occupancy / prefetch variants regressed or were neutral.
__global__ void aggregate_kernel(const float* __restrict__ We,
                                 const float* __restrict__ skipIn,
                                 float* __restrict__ out,
                                 int applyLeaky) {
    int w = (blockIdx.x * blockDim.x + threadIdx.x) >> 5;
    int lane = threadIdx.x & 31;
    if (w >= N_NODES) return;
    int g = lane >> 3, r = lane & 7;
    unsigned gmask = 0xFFu << (g * 8);

    float2 we0[4], we1[4];
    {
        const float2* We2 = reinterpret_cast<const float2*>(We);
#pragma unroll
        for (int i = 0; i < 4; i++) {
            we0[i] = We2[4 * r + i];        // row 0
            we1[i] = We2[32 + 4 * r + i];   // row 1
        }
    }

    float2 q2[4];
    {
        const float4* qrow = reinterpret_cast<const float4*>(g_q) + (size_t)w * 16;
        float4 q0 = qrow[2 * r], q1 = qrow[2 * r + 1];
        q2[0] = make_float2(q0.x, q0.y); q2[1] = make_float2(q0.z, q0.w);
        q2[2] = make_float2(q1.x, q1.y); q2[3] = make_float2(q1.z, q1.w);
    }

    const uint4* kbase = reinterpret_cast<const uint4*>(g_kbf);  // 8 uint4 per row
    const uint4* vbase = reinterpret_cast<const uint4*>(g_vbf);  // 8 uint4 per row

    float den = 0.f;
    float2 acc[4];
#pragma unroll
    for (int i = 0; i < 4; i++) acc[i] = make_float2(0.f, 0.f);

    int beg = g_off[w];
    int end = g_off[w + 1];
    for (int j = beg + g; j < end; j += 4) {
        int s = g_srcs[j];
        float2 ea = g_ea[j];
        float2 eax = make_float2(ea.x, ea.x), eay = make_float2(ea.y, ea.y);
        uint4 kp = kbase[(size_t)s * 8 + r];  // 8 bf16 channels = 16B
        uint4 vp = vbase[(size_t)s * 8 + r];  // 8 bf16 channels = 16B
        float2 k2[4] = {
            __bfloat1622float2(*reinterpret_cast<__nv_bfloat162*>(&kp.x)),
            __bfloat1622float2(*reinterpret_cast<__nv_bfloat162*>(&kp.y)),
            __bfloat1622float2(*reinterpret_cast<__nv_bfloat162*>(&kp.z)),
            __bfloat1622float2(*reinterpret_cast<__nv_bfloat162*>(&kp.w))
        };
        float2 v2[4] = {
            __bfloat1622float2(*reinterpret_cast<__nv_bfloat162*>(&vp.x)),
            __bfloat1622float2(*reinterpret_cast<__nv_bfloat162*>(&vp.y)),
            __bfloat1622float2(*reinterpret_cast<__nv_bfloat162*>(&vp.z)),
            __bfloat1622float2(*reinterpret_cast<__nv_bfloat162*>(&vp.w))
        };

        float2 e2[4];
        float2 d2 = make_float2(0.f, 0.f);
#pragma unroll
        for (int i = 0; i < 4; i++) {
            e2[i] = ffma2(eay, we1[i], fmul2(eax, we0[i]));
            d2 = ffma2(q2[i], fadd2(k2[i], e2[i]), d2);
        }
        float part = d2.x + d2.y;
        part += __shfl_xor_sync(gmask, part, 1);
        part += __shfl_xor_sync(gmask, part, 2);
        part += __shfl_xor_sync(gmask, part, 4);
        float p = __expf(part * 0.125f);  // 1/sqrt(64)
        den += p;
        float2 p2 = make_float2(p, p);
#pragma unroll
        for (int i = 0; i < 4; i++)
            acc[i] = ffma2(p2, fadd2(v2[i], e2[i]), acc[i]);
    }

    // reconverge, then sum-merge the 4 group states
    __syncwarp();
#pragma unroll
    for (int off = 8; off <= 16; off <<= 1) {
        den += __shfl_xor_sync(0xffffffffu, den, off);
#pragma unroll
        for (int i = 0; i < 4; i++) {
            acc[i].x += __shfl_xor_sync(0xffffffffu, acc[i].x, off);
            acc[i].y += __shfl_xor_sync(0xffffffffu, acc[i].y, off);
        }
    }

    if (g == 0) {
        float inv = 1.0f / (den + 1e-16f);
        const float4* sk = reinterpret_cast<const float4*>(skipIn) + (size_t)w * 16;
        float4 s0 = sk[2 * r], s1 = sk[2 * r + 1];
        float4 o0, o1;
        o0.x = acc[0].x * inv + s0.x; o0.y = acc[0].y * inv + s0.y;
        o0.z = acc[1].x * inv + s0.z; o0.w = acc[1].y * inv + s0.w;
        o1.x = acc[2].x * inv + s1.x; o1.y = acc[2].y * inv + s1.y;
        o1.z = acc[3].x * inv + s1.z; o1.w = acc[3].y * inv + s1.w;
        if (applyLeaky) {
            o0.x = leakyf(o0.x); o0.y = leakyf(o0.y); o0.z = leakyf(o0.z); o0.w = leakyf(o0.w);
            o1.x = leakyf(o1.x); o1.y = leakyf(o1.y); o1.z = leakyf(o1.z); o1.w = leakyf(o1.w);
        }
        float4* orow = reinterpret_cast<float4*>(out) + (size_t)w * 16;
        orow[2 * r] = o0;
        orow[2 * r + 1] = o1;
    }
}

// ---------------- batch norm ----------------
__global__ void bn_stats_kernel(const float* __restrict__ o) {
    int c = threadIdx.x & 63;
    int rowsPerBlk = blockDim.x >> 6;
    int r = blockIdx.x * rowsPerBlk + (threadIdx.x >> 6);
    float s = 0.f, ss = 0.f;
    for (; r < N_NODES; r += gridDim.x * rowsPerBlk) {
        float v = o[r * H + c];
        s += v;
        ss += v * v;
    }
    atomicAdd(&g_bnsum[c], s);
    atomicAdd(&g_bnsq[c], ss);
}

__global__ void bn_apply_kernel(const float* __restrict__ o,
                                const float* __restrict__ gamma,
                                const float* __restrict__ beta,
                                float* __restrict__ h) {
    int idx = blockIdx.x * blockDim.x + threadIdx.x;
    if (idx >= N_NODES * H) return;
    int c = idx & 63;
    const float invN = 1.0f / (float)N_NODES;
    float mean = g_bnsum[c] * invN;
    float var = g_bnsq[c] * invN - mean * mean;
    float sc = gamma[c] * rsqrtf(var + 1e-5f);
    h[idx] = leakyf((o[idx] - mean) * sc + beta[c]);
}

// ---------------- final MLP head (64 -> 32 -> 1) * mask ----------------
__global__ void mlp_kernel(const float* __restrict__ h,
                           const float* __restrict__ Wf1, const float* __restrict__ bf1,
                           const float* __restrict__ Wf2, const float* __restrict__ bf2,
                           const float* __restrict__ mask,
                           float* __restrict__ out) {
    int w = (blockIdx.x * blockDim.x + threadIdx.x) >> 5;
    int lane = threadIdx.x & 31;
    if (w >= N_NODES) return;
    float2 myh = reinterpret_cast<const float2*>(h)[w * 32 + lane];
    float acc = bf1[lane];
#pragma unroll 4
    for (int kk = 0; kk < 32; kk++) {
        float hx = __shfl_sync(0xffffffffu, myh.x, kk);
        float hy = __shfl_sync(0xffffffffu, myh.y, kk);
        acc += hx * Wf1[(2 * kk) * 32 + lane] + hy * Wf1[(2 * kk + 1) * 32 + lane];
    }
    acc = leakyf(acc);
    float r = acc * Wf2[lane];
#pragma unroll
    for (int o = 16; o > 0; o >>= 1)
        r += __shfl_xor_sync(0xffffffffu, r, o);
    if (lane == 0) out[w] = (r + bf2[0]) * mask[w];
}

// ---------------- launch ----------------
extern "C" void kernel_launch(void* const* d_in, const int* in_sizes, int n_in,
                              void* d_out, int out_size) {
    const float* x         = (const float*)d_in[0];
    const int*   edge_index= (const int*)d_in[1];
    const float* edge_attr = (const float*)d_in[2];
    const float* mask      = (const float*)d_in[3];
    const float* Wq1 = (const float*)d_in[4];  const float* bq1 = (const float*)d_in[5];
    const float* Wk1 = (const float*)d_in[6];  const float* bk1 = (const float*)d_in[7];
    const float* Wv1 = (const float*)d_in[8];  const float* bv1 = (const float*)d_in[9];
    const float* We1 = (const float*)d_in[10];
    const float* Ws1 = (const float*)d_in[11]; const float* bs1 = (const float*)d_in[12];
    const float* Wq2 = (const float*)d_in[13]; const float* bq2 = (const float*)d_in[14];
    const float* Wk2 = (const float*)d_in[15]; const float* bk2 = (const float*)d_in[16];
    const float* Wv2 = (const float*)d_in[17]; const float* bv2 = (const float*)d_in[18];
    const float* We2 = (const float*)d_in[19];
    const float* Ws2 = (const float*)d_in[20]; const float* bs2 = (const float*)d_in[21];
    const float* bn_gamma = (const float*)d_in[22];
    const float* bn_beta  = (const float*)d_in[23];
    const float* Wf1 = (const float*)d_in[24]; const float* bf1 = (const float*)d_in[25];
    const float* Wf2 = (const float*)d_in[26]; const float* bf2 = (const float*)d_in[27];
    float* out = (float*)d_out;

    // real device addresses of scratch symbols (host shadow address is the
    // silent-wrong-data trap on GB300/ATS)
    void* p = nullptr;
    cudaGetSymbolAddress(&p, g_o);  float* o_dev = (float*)p;
    cudaGetSymbolAddress(&p, g_h);  float* h_dev = (float*)p;

    const int TB = 256;
    const int edgeBlocks = (N_EDGES + TB - 1) / TB;
    const int nhBlocks   = (N_NODES * H + TB - 1) / TB;
    const int warpBlocks = (N_NODES * 32 + TB - 1) / TB;
    const int t1Blocks   = (N_NODES * 16 + TB - 1) / TB;
    const int t2Blocks   = (N_NODES + 31) / 32;

    // ---- CSR build (g_cnt arrives zeroed: BSS at start, re-zeroed by scan_fill) ----
    hist_kernel<<<edgeBlocks, TB>>>(edge_index);
    scan_block_sums<<<SCAN_NB, 256>>>();
    scan_partials<<<1, 512>>>();
    scan_fill<<<SCAN_NB, 256>>>();   // also zeroes g_cnt + BN accumulators
    scatter_kernel<<<edgeBlocks, TB>>>(edge_index, edge_attr);

    // ---- conv1 (in=2) ----
    transform1_kernel<<<t1Blocks, TB>>>(x, Wq1, bq1, Wk1, bk1, Wv1, bv1, Ws1, bs1);
    aggregate_kernel<<<warpBlocks, TB>>>(We1, o_dev /*skip*/, o_dev /*out*/, 0);

    // ---- batch norm + leaky -> g_h ----
    bn_stats_kernel<<<512, TB>>>(o_dev);
    bn_apply_kernel<<<nhBlocks, TB>>>(o_dev, bn_gamma, bn_beta, h_dev);

    // ---- conv2 x 3, leaky fused ----
    for (int it = 0; it < 3; it++) {
        transform2_kernel<<<t2Blocks, TB>>>(h_dev, Wq2, bq2, Wk2, bk2, Wv2, bv2, Ws2, bs2);
        aggregate_kernel<<<warpBlocks, TB>>>(We2, o_dev /*skip*/, h_dev /*out*/, 1);
    }

    // ---- MLP head ----
    mlp_kernel<<<warpBlocks, TB>>>(h_dev, Wf1, bf1, Wf2, bf2, mask, out);

    (void)in_sizes; (void)n_in; (void)out_size;
}

// round 17
// speedup vs baseline: 1.4733x; 1.4733x over previous
#include <cuda_runtime.h>
#include <cuda_bf16.h>

#define N_NODES 100000
#define N_EDGES 1600000
#define H 64
#define SCAN_NB ((N_NODES + 255) / 256)   // 391

// ---------------- scratch (device globals; no allocation allowed) ----------------
__device__ float g_q[N_NODES * H];
__device__ __nv_bfloat16 g_kbf[N_NODES * H];  // k in bf16 (gathered 16x per node)
__device__ __nv_bfloat16 g_vbf[N_NODES * H];  // v in bf16 (gathered 16x per node)
__device__ float g_h[N_NODES * H];   // current node features
__device__ float g_o[N_NODES * H];   // skip accumulator / conv1 output
__device__ int   g_cnt[N_NODES];     // zero at process start (BSS); re-zeroed by scan_fill each launch
__device__ int   g_off[N_NODES + 1];
__device__ int   g_cur[N_NODES];
__device__ int   g_srcs[N_EDGES];    // CSR-permuted sources (fp32 path — precision budget closed)
__device__ float2 g_ea[N_EDGES];     // CSR-permuted edge_attr (fp32)
__device__ float g_bnsum[H];
__device__ float g_bnsq[H];
__device__ int   g_bsum[512];
__device__ int   g_bpre[512];

__device__ __forceinline__ float leakyf(float x) { return x >= 0.f ? x : 0.01f * x; }

// ---- packed f32x2 ops (Blackwell FFMA2/FADD2/FMUL2; PTX-only) ----
__device__ __forceinline__ float2 ffma2(float2 a, float2 b, float2 c) {
    float2 d;
    asm("fma.rn.f32x2 %0, %1, %2, %3;"
        : "=l"(*reinterpret_cast<unsigned long long*>(&d))
        : "l"(*reinterpret_cast<unsigned long long*>(&a)),
          "l"(*reinterpret_cast<unsigned long long*>(&b)),
          "l"(*reinterpret_cast<unsigned long long*>(&c)));
    return d;
}
__device__ __forceinline__ float2 fadd2(float2 a, float2 b) {
    float2 d;
    asm("add.rn.f32x2 %0, %1, %2;"
        : "=l"(*reinterpret_cast<unsigned long long*>(&d))
        : "l"(*reinterpret_cast<unsigned long long*>(&a)),
          "l"(*reinterpret_cast<unsigned long long*>(&b)));
    return d;
}
__device__ __forceinline__ float2 fmul2(float2 a, float2 b) {
    float2 d;
    asm("mul.rn.f32x2 %0, %1, %2;"
        : "=l"(*reinterpret_cast<unsigned long long*>(&d))
        : "l"(*reinterpret_cast<unsigned long long*>(&a)),
          "l"(*reinterpret_cast<unsigned long long*>(&b)));
    return d;
}

// ---------------- CSR build ----------------
__global__ void hist_kernel(const int* __restrict__ edge_index) {
    int i = blockIdx.x * blockDim.x + threadIdx.x;
    if (i >= N_EDGES) return;
    int t = edge_index[N_EDGES + i];
    atomicAdd(&g_cnt[t], 1);
}

// 3-phase parallel exclusive scan of g_cnt -> g_off / g_cur
__global__ void scan_block_sums() {
    __shared__ int sh[256];
    int i = blockIdx.x * 256 + threadIdx.x;
    int v = (i < N_NODES) ? g_cnt[i] : 0;
    sh[threadIdx.x] = v;
    __syncthreads();
    for (int o = 128; o > 0; o >>= 1) {
        if (threadIdx.x < o) sh[threadIdx.x] += sh[threadIdx.x + o];
        __syncthreads();
    }
    if (threadIdx.x == 0) g_bsum[blockIdx.x] = sh[0];
}

__global__ void scan_partials() {   // 1 block, 512 threads
    __shared__ int sh[512];
    int t = threadIdx.x;
    int v = (t < SCAN_NB) ? g_bsum[t] : 0;
    sh[t] = v;
    __syncthreads();
    for (int o = 1; o < 512; o <<= 1) {
        int u = (t >= o) ? sh[t - o] : 0;
        __syncthreads();
        sh[t] += u;
        __syncthreads();
    }
    g_bpre[t] = sh[t] - v;  // exclusive prefix of block t
    if (t == SCAN_NB - 1) g_off[N_NODES] = sh[t];
}

// also re-zeroes g_cnt (for next launch) and the BN accumulators (used later
// in THIS launch by bn_stats). Deterministic: g_cnt starts zero (BSS) and is
// returned to zero by every launch before it ends.
__global__ void scan_fill() {
    __shared__ int sh[256];
    int t = threadIdx.x;
    int i = blockIdx.x * 256 + t;
    int v = (i < N_NODES) ? g_cnt[i] : 0;
    sh[t] = v;
    __syncthreads();
    for (int o = 1; o < 256; o <<= 1) {
        int u = (t >= o) ? sh[t - o] : 0;
        __syncthreads();
        sh[t] += u;
        __syncthreads();
    }
    int excl = sh[t] - v + g_bpre[blockIdx.x];
    if (i < N_NODES) { g_off[i] = excl; g_cur[i] = excl; g_cnt[i] = 0; }
    if (blockIdx.x == 0 && t < H) { g_bnsum[t] = 0.f; g_bnsq[t] = 0.f; }
}

__global__ void scatter_kernel(const int* __restrict__ edge_index,
                               const float* __restrict__ edge_attr) {
    int i = blockIdx.x * blockDim.x + threadIdx.x;
    if (i >= N_EDGES) return;
    int t = edge_index[N_EDGES + i];
    int p = atomicAdd(&g_cur[t], 1);
    g_srcs[p] = edge_index[i];
    g_ea[p] = reinterpret_cast<const float2*>(edge_attr)[i];
}

// ---------------- node transforms ----------------
// conv1: in-dim 2. one thread per (node, 4 channels). float4; k,v stored bf16.
__global__ void transform1_kernel(const float* __restrict__ x,
                                  const float* __restrict__ Wq, const float* __restrict__ bq,
                                  const float* __restrict__ Wk, const float* __restrict__ bk,
                                  const float* __restrict__ Wv, const float* __restrict__ bv,
                                  const float* __restrict__ Ws, const float* __restrict__ bs) {
    int idx = blockIdx.x * blockDim.x + threadIdx.x;
    if (idx >= N_NODES * 16) return;
    int c4 = idx & 15;            // which float4 of the 16 per row
    int n = idx >> 4;
    float2 xv = reinterpret_cast<const float2*>(x)[n];
    const float4* Wq4 = (const float4*)Wq; const float4* bq4 = (const float4*)bq;
    const float4* Wk4 = (const float4*)Wk; const float4* bk4 = (const float4*)bk;
    const float4* Wv4 = (const float4*)Wv; const float4* bv4 = (const float4*)bv;
    const float4* Ws4 = (const float4*)Ws; const float4* bs4 = (const float4*)bs;
    float4 w0, w1, b, r;
#define T1C(W4, B4) \
    w0 = W4[c4]; w1 = W4[16 + c4]; b = B4[c4]; \
    r.x = xv.x * w0.x + xv.y * w1.x + b.x; \
    r.y = xv.x * w0.y + xv.y * w1.y + b.y; \
    r.z = xv.x * w0.z + xv.y * w1.z + b.z; \
    r.w = xv.x * w0.w + xv.y * w1.w + b.w;
#define PACK_BF16_STORE(DST) \
    { \
        __nv_bfloat162 lo = __float22bfloat162_rn(make_float2(r.x, r.y)); \
        __nv_bfloat162 hi = __float22bfloat162_rn(make_float2(r.z, r.w)); \
        uint2 pk; \
        pk.x = *reinterpret_cast<unsigned int*>(&lo); \
        pk.y = *reinterpret_cast<unsigned int*>(&hi); \
        reinterpret_cast<uint2*>(DST)[idx] = pk; \
    }
    T1C(Wq4, bq4) reinterpret_cast<float4*>(g_q)[idx] = r;
    T1C(Wk4, bk4) PACK_BF16_STORE(g_kbf)
    T1C(Wv4, bv4) PACK_BF16_STORE(g_vbf)
    T1C(Ws4, bs4) reinterpret_cast<float4*>(g_o)[idx] = r;
#undef PACK_BF16_STORE
#undef T1C
}

// conv2: in-dim 64. 4 nodes per warp, h staged in smem, packed f32x2 FMAs.
// (R5/R14 structure — LOCKED; weights via LDG = L1-resident, R16 smem staging
// regressed badly.) NEW: optional fused BN+leaky applied during h staging
// (replaces the separate bn_apply kernel for the first conv2 call; identical
// fp32 expression element-for-element).
__global__ void transform2_kernel(const float* __restrict__ h,
                                  const float* __restrict__ Wq, const float* __restrict__ bq,
                                  const float* __restrict__ Wk, const float* __restrict__ bk,
                                  const float* __restrict__ Wv, const float* __restrict__ bv,
                                  const float* __restrict__ Ws, const float* __restrict__ bs,
                                  const float* __restrict__ gamma,
                                  const float* __restrict__ beta,
                                  int useBN) {
    __shared__ float hs[32 * H];  // 32 nodes per block
    int tid = threadIdx.x;
    int nodeBase = blockIdx.x * 32;
    const float invN = 1.0f / (float)N_NODES;
    for (int i = tid; i < 32 * 16; i += 256) {
        int n = nodeBase + (i >> 4);
        float4 val = (n < N_NODES) ? reinterpret_cast<const float4*>(h)[n * 16 + (i & 15)]
                                   : make_float4(0.f, 0.f, 0.f, 0.f);
        if (useBN) {
            int c = (i & 15) * 4;  // first channel of this float4
#define BN1(F, CC) { \
            float mean = g_bnsum[CC] * invN; \
            float var = g_bnsq[CC] * invN - mean * mean; \
            float sc = gamma[CC] * rsqrtf(var + 1e-5f); \
            F = leakyf((F - mean) * sc + beta[CC]); }
            BN1(val.x, c)
            BN1(val.y, c + 1)
            BN1(val.z, c + 2)
            BN1(val.w, c + 3)
#undef BN1
        }
        reinterpret_cast<float4*>(hs)[i] = val;
    }
    __syncthreads();

    int wid = tid >> 5, lane = tid & 31;
    int nloc = wid * 4;           // local node base within block
    float2 aq[4], ak[4], av[4], ao[4];
    float2 bqv = reinterpret_cast<const float2*>(bq)[lane];
    float2 bkv = reinterpret_cast<const float2*>(bk)[lane];
    float2 bvv = reinterpret_cast<const float2*>(bv)[lane];
    float2 bsv = reinterpret_cast<const float2*>(bs)[lane];
#pragma unroll
    for (int nn = 0; nn < 4; nn++) { aq[nn] = bqv; ak[nn] = bkv; av[nn] = bvv; ao[nn] = bsv; }

    const float2* hs2 = reinterpret_cast<const float2*>(hs);
#pragma unroll 4
    for (int kk = 0; kk < 32; kk++) {
        float2 w0q = reinterpret_cast<const float2*>(Wq + (2 * kk) * H)[lane];
        float2 w1q = reinterpret_cast<const float2*>(Wq + (2 * kk + 1) * H)[lane];
        float2 w0k = reinterpret_cast<const float2*>(Wk + (2 * kk) * H)[lane];
        float2 w1k = reinterpret_cast<const float2*>(Wk + (2 * kk + 1) * H)[lane];
        float2 w0v = reinterpret_cast<const float2*>(Wv + (2 * kk) * H)[lane];
        float2 w1v = reinterpret_cast<const float2*>(Wv + (2 * kk + 1) * H)[lane];
        float2 w0s = reinterpret_cast<const float2*>(Ws + (2 * kk) * H)[lane];
        float2 w1s = reinterpret_cast<const float2*>(Ws + (2 * kk + 1) * H)[lane];
#pragma unroll
        for (int nn = 0; nn < 4; nn++) {
            float2 hxy = hs2[(nloc + nn) * 32 + kk];  // smem broadcast
            float2 hx2 = make_float2(hxy.x, hxy.x);
            float2 hy2 = make_float2(hxy.y, hxy.y);
            aq[nn] = ffma2(hy2, w1q, ffma2(hx2, w0q, aq[nn]));
            ak[nn] = ffma2(hy2, w1k, ffma2(hx2, w0k, ak[nn]));
            av[nn] = ffma2(hy2, w1v, ffma2(hx2, w0v, av[nn]));
            ao[nn] = ffma2(hy2, w1s, ffma2(hx2, w0s, ao[nn]));
        }
    }
#pragma unroll
    for (int nn = 0; nn < 4; nn++) {
        int n = nodeBase + nloc + nn;
        if (n < N_NODES) {
            reinterpret_cast<float2*>(g_q)[n * 32 + lane] = aq[nn];
            __nv_bfloat162 kb = __float22bfloat162_rn(ak[nn]);
            reinterpret_cast<__nv_bfloat162*>(g_kbf)[n * 32 + lane] = kb;
            __nv_bfloat162 vb = __float22bfloat162_rn(av[nn]);
            reinterpret_cast<__nv_bfloat162*>(g_vbf)[n * 32 + lane] = vb;
            reinterpret_cast<float2*>(g_o)[n * 32 + lane] = ao[nn];
        }
    }
}

// ---------------- fused attention aggregation (R11/R14 champion — LOCKED) ----
// warp per target node; 4 sub-groups of 8 lanes, one edge per group per iter;
// plain exp (shift-invariant softmax, bounded scores); packed f32x2; sum-merge.
// Intra-group shfls use the GROUP mask (groups have different trip counts).
__global__ void aggregate_kernel(const float* __restrict__ We,
                                 const float* __restrict__ skipIn,
                                 float* __restrict__ out,
                                 int applyLeaky) {
    int w = (blockIdx.x * blockDim.x + threadIdx.x) >> 5;
    int lane = threadIdx.x & 31;
    if (w >= N_NODES) return;
    int g = lane >> 3, r = lane & 7;
    unsigned gmask = 0xFFu << (g * 8);

    float2 we0[4], we1[4];
    {
        const float2* We2 = reinterpret_cast<const float2*>(We);
#pragma unroll
        for (int i = 0; i < 4; i++) {
            we0[i] = We2[4 * r + i];        // row 0
            we1[i] = We2[32 + 4 * r + i];   // row 1
        }
    }

    float2 q2[4];
    {
        const float4* qrow = reinterpret_cast<const float4*>(g_q) + (size_t)w * 16;
        float4 q0 = qrow[2 * r], q1 = qrow[2 * r + 1];
        q2[0] = make_float2(q0.x, q0.y); q2[1] = make_float2(q0.z, q0.w);
        q2[2] = make_float2(q1.x, q1.y); q2[3] = make_float2(q1.z, q1.w);
    }

    const uint4* kbase = reinterpret_cast<const uint4*>(g_kbf);  // 8 uint4 per row
    const uint4* vbase = reinterpret_cast<const uint4*>(g_vbf);  // 8 uint4 per row

    float den = 0.f;
    float2 acc[4];
#pragma unroll
    for (int i = 0; i < 4; i++) acc[i] = make_float2(0.f, 0.f);

    int beg = g_off[w];
    int end = g_off[w + 1];
    for (int j = beg + g; j < end; j += 4) {
        int s = g_srcs[j];
        float2 ea = g_ea[j];
        float2 eax = make_float2(ea.x, ea.x), eay = make_float2(ea.y, ea.y);
        uint4 kp = kbase[(size_t)s * 8 + r];  // 8 bf16 channels = 16B
        uint4 vp = vbase[(size_t)s * 8 + r];  // 8 bf16 channels = 16B
        float2 k2[4] = {
            __bfloat1622float2(*reinterpret_cast<__nv_bfloat162*>(&kp.x)),
            __bfloat1622float2(*reinterpret_cast<__nv_bfloat162*>(&kp.y)),
            __bfloat1622float2(*reinterpret_cast<__nv_bfloat162*>(&kp.z)),
            __bfloat1622float2(*reinterpret_cast<__nv_bfloat162*>(&kp.w))
        };
        float2 v2[4] = {
            __bfloat1622float2(*reinterpret_cast<__nv_bfloat162*>(&vp.x)),
            __bfloat1622float2(*reinterpret_cast<__nv_bfloat162*>(&vp.y)),
            __bfloat1622float2(*reinterpret_cast<__nv_bfloat162*>(&vp.z)),
            __bfloat1622float2(*reinterpret_cast<__nv_bfloat162*>(&vp.w))
        };

        float2 e2[4];
        float2 d2 = make_float2(0.f, 0.f);
#pragma unroll
        for (int i = 0; i < 4; i++) {
            e2[i] = ffma2(eay, we1[i], fmul2(eax, we0[i]));
            d2 = ffma2(q2[i], fadd2(k2[i], e2[i]), d2);
        }
        float part = d2.x + d2.y;
        part += __shfl_xor_sync(gmask, part, 1);
        part += __shfl_xor_sync(gmask, part, 2);
        part += __shfl_xor_sync(gmask, part, 4);
        float p = __expf(part * 0.125f);  // 1/sqrt(64)
        den += p;
        float2 p2 = make_float2(p, p);
#pragma unroll
        for (int i = 0; i < 4; i++)
            acc[i] = ffma2(p2, fadd2(v2[i], e2[i]), acc[i]);
    }

    // reconverge, then sum-merge the 4 group states
    __syncwarp();
#pragma unroll
    for (int off = 8; off <= 16; off <<= 1) {
        den += __shfl_xor_sync(0xffffffffu, den, off);
#pragma unroll
        for (int i = 0; i < 4; i++) {
            acc[i].x += __shfl_xor_sync(0xffffffffu, acc[i].x, off);
            acc[i].y += __shfl_xor_sync(0xffffffffu, acc[i].y, off);
        }
    }

    if (g == 0) {
        float inv = 1.0f / (den + 1e-16f);
        const float4* sk = reinterpret_cast<const float4*>(skipIn) + (size_t)w * 16;
        float4 s0 = sk[2 * r], s1 = sk[2 * r + 1];
        float4 o0, o1;
        o0.x = acc[0].x * inv + s0.x; o0.y = acc[0].y * inv + s0.y;
        o0.z = acc[1].x * inv + s0.z; o0.w = acc[1].y * inv + s0.w;
        o1.x = acc[2].x * inv + s1.x; o1.y = acc[2].y * inv + s1.y;
        o1.z = acc[3].x * inv + s1.z; o1.w = acc[3].y * inv + s1.w;
        if (applyLeaky) {
            o0.x = leakyf(o0.x); o0.y = leakyf(o0.y); o0.z = leakyf(o0.z); o0.w = leakyf(o0.w);
            o1.x = leakyf(o1.x); o1.y = leakyf(o1.y); o1.z = leakyf(o1.z); o1.w = leakyf(o1.w);
        }
        float4* orow = reinterpret_cast<float4*>(out) + (size_t)w * 16;
        orow[2 * r] = o0;
        orow[2 * r + 1] = o1;
    }
}

// ---------------- batch norm stats ----------------
__global__ void bn_stats_kernel(const float* __restrict__ o) {
    int c = threadIdx.x & 63;
    int rowsPerBlk = blockDim.x >> 6;
    int r = blockIdx.x * rowsPerBlk + (threadIdx.x >> 6);
    float s = 0.f, ss = 0.f;
    for (; r < N_NODES; r += gridDim.x * rowsPerBlk) {
        float v = o[r * H + c];
        s += v;
        ss += v * v;
    }
    atomicAdd(&g_bnsum[c], s);
    atomicAdd(&g_bnsq[c], ss);
}

// ---------------- final MLP head (64 -> 32 -> 1) * mask ----------------
__global__ void mlp_kernel(const float* __restrict__ h,
                           const float* __restrict__ Wf1, const float* __restrict__ bf1,
                           const float* __restrict__ Wf2, const float* __restrict__ bf2,
                           const float* __restrict__ mask,
                           float* __restrict__ out) {
    int w = (blockIdx.x * blockDim.x + threadIdx.x) >> 5;
    int lane = threadIdx.x & 31;
    if (w >= N_NODES) return;
    float2 myh = reinterpret_cast<const float2*>(h)[w * 32 + lane];
    float acc = bf1[lane];
#pragma unroll 4
    for (int kk = 0; kk < 32; kk++) {
        float hx = __shfl_sync(0xffffffffu, myh.x, kk);
        float hy = __shfl_sync(0xffffffffu, myh.y, kk);
        acc += hx * Wf1[(2 * kk) * 32 + lane] + hy * Wf1[(2 * kk + 1) * 32 + lane];
    }
    acc = leakyf(acc);
    float r = acc * Wf2[lane];
#pragma unroll
    for (int o = 16; o > 0; o >>= 1)
        r += __shfl_xor_sync(0xffffffffu, r, o);
    if (lane == 0) out[w] = (r + bf2[0]) * mask[w];
}

// ---------------- launch ----------------
extern "C" void kernel_launch(void* const* d_in, const int* in_sizes, int n_in,
                              void* d_out, int out_size) {
    const float* x         = (const float*)d_in[0];
    const int*   edge_index= (const int*)d_in[1];
    const float* edge_attr = (const float*)d_in[2];
    const float* mask      = (const float*)d_in[3];
    const float* Wq1 = (const float*)d_in[4];  const float* bq1 = (const float*)d_in[5];
    const float* Wk1 = (const float*)d_in[6];  const float* bk1 = (const float*)d_in[7];
    const float* Wv1 = (const float*)d_in[8];  const float* bv1 = (const float*)d_in[9];
    const float* We1 = (const float*)d_in[10];
    const float* Ws1 = (const float*)d_in[11]; const float* bs1 = (const float*)d_in[12];
    const float* Wq2 = (const float*)d_in[13]; const float* bq2 = (const float*)d_in[14];
    const float* Wk2 = (const float*)d_in[15]; const float* bk2 = (const float*)d_in[16];
    const float* Wv2 = (const float*)d_in[17]; const float* bv2 = (const float*)d_in[18];
    const float* We2 = (const float*)d_in[19];
    const float* Ws2 = (const float*)d_in[20]; const float* bs2 = (const float*)d_in[21];
    const float* bn_gamma = (const float*)d_in[22];
    const float* bn_beta  = (const float*)d_in[23];
    const float* Wf1 = (const float*)d_in[24]; const float* bf1 = (const float*)d_in[25];
    const float* Wf2 = (const float*)d_in[26]; const float* bf2 = (const float*)d_in[27];
    float* out = (float*)d_out;

    // real device addresses of scratch symbols (host shadow address is the
    // silent-wrong-data trap on GB300/ATS)
    void* p = nullptr;
    cudaGetSymbolAddress(&p, g_o);  float* o_dev = (float*)p;
    cudaGetSymbolAddress(&p, g_h);  float* h_dev = (float*)p;

    const int TB = 256;
    const int edgeBlocks = (N_EDGES + TB - 1) / TB;
    const int warpBlocks = (N_NODES * 32 + TB - 1) / TB;
    const int t1Blocks   = (N_NODES * 16 + TB - 1) / TB;
    const int t2Blocks   = (N_NODES + 31) / 32;

    // ---- CSR build (g_cnt arrives zeroed: BSS at start, re-zeroed by scan_fill) ----
    hist_kernel<<<edgeBlocks, TB>>>(edge_index);
    scan_block_sums<<<SCAN_NB, 256>>>();
    scan_partials<<<1, 512>>>();
    scan_fill<<<SCAN_NB, 256>>>();   // also zeroes g_cnt + BN accumulators
    scatter_kernel<<<edgeBlocks, TB>>>(edge_index, edge_attr);

    // ---- conv1 (in=2) ----
    transform1_kernel<<<t1Blocks, TB>>>(x, Wq1, bq1, Wk1, bk1, Wv1, bv1, Ws1, bs1);
    aggregate_kernel<<<warpBlocks, TB>>>(We1, o_dev /*skip*/, o_dev /*out*/, 0);

    // ---- batch norm stats (apply fused into first transform2 staging) ----
    bn_stats_kernel<<<512, TB>>>(o_dev);

    // ---- conv2 x 3, leaky fused; first call applies BN inline while staging ----
    transform2_kernel<<<t2Blocks, TB>>>(o_dev, Wq2, bq2, Wk2, bk2, Wv2, bv2, Ws2, bs2,
                                        bn_gamma, bn_beta, 1);
    aggregate_kernel<<<warpBlocks, TB>>>(We2, o_dev /*skip*/, h_dev /*out*/, 1);
    for (int it = 1; it < 3; it++) {
        transform2_kernel<<<t2Blocks, TB>>>(h_dev, Wq2, bq2, Wk2, bk2, Wv2, bv2, Ws2, bs2,
                                            bn_gamma, bn_beta, 0);
        aggregate_kernel<<<warpBlocks, TB>>>(We2, o_dev /*skip*/, h_dev /*out*/, 1);
    }

    // ---- MLP head ----
    mlp_kernel<<<warpBlocks, TB>>>(h_dev, Wf1, bf1, Wf2, bf2, mask, out);

    (void)in_sizes; (void)n_in; (void)out_size;
}